// round 12
// baseline (speedup 1.0000x reference)
#include <cuda_runtime.h>
#include <cuda_bf16.h>
#include <cuda_fp16.h>

// GCNLayer SpMM: out[i,:] = sum_{e: rows[e]==i} vals[e] * embeds[cols[e],:]
// N=10000 nodes, E=640000 edges, D=128 features.
//
// Round-11: rounds 9/10 proved the fp32 spmm sits AT the practical LTS cap
// (~6300 B/cyc): 337MB -> 28.5us, invariant under 8x more parallelism. Only
// fewer bytes win. fp16 gather halves traffic; round-8 showed per-element
// F2F conversion (82M slow-pipe ops ~= 18us) eats the gain, so this version
// accumulates with HFMA2 (fast fma pipe) in fp16 pairs and flushes to fp32
// every 8 edges (F2F count /64). Edge weight pre-rounded to half2(v,v) in
// scatter. Expected rel_err ~4e-4 (vs 1e-3 gate). Also: memset nodes
// eliminated (hist zeroes g_alloc, span re-zeroes g_count for the next graph
// replay), hist/scatter process 2 edges per thread.

static constexpr int MAX_N = 10000;
static constexpr int MAX_E = 640000;
static constexpr int D_FEAT = 128;
static constexpr int C_REP = 32;           // counter replication factor

__device__ int     g_count[MAX_N * C_REP];   // [row][replica] (zero at steady state)
__device__ int     g_cursor[MAX_N * C_REP];  // [row][replica] staggered cursors
__device__ int2    g_span[MAX_N];            // .x = start, .y = end (unordered CSR)
__device__ int     g_alloc;                  // bump allocator head
__device__ uint2   g_pairs[MAX_E];           // .x = col, .y = half2(v,v)
__device__ __half  g_emb16[MAX_N * D_FEAT];  // fp16 embedding cache

// ---------------------------------------------------------------- convert
// embeds fp32 -> fp16 cache. One half2 per thread.
__global__ void convert_kernel(const float2* __restrict__ emb, int n2) {
    int i = blockIdx.x * blockDim.x + threadIdx.x;
    if (i < n2) {
        float2 f = emb[i];
        ((__half2*)g_emb16)[i] = __floats2half2_rn(f.x, f.y);
    }
}

// ---------------------------------------------------------------- hist
// 2 edges/thread. No-return atomicAdd -> RED; replica = e&31 keeps every
// lane of a warp on a different word of the row's 128B counter group.
// Thread 0 also resets the bump allocator for this replay.
__global__ void hist_kernel(const int2* __restrict__ rows2, int E2) {
    int i = blockIdx.x * blockDim.x + threadIdx.x;
    if (i == 0) g_alloc = 0;
    if (i < E2) {
        int2 r = rows2[i];
        int e0 = 2 * i;
        atomicAdd(&g_count[r.x * C_REP + (e0 & (C_REP - 1))], 1);
        atomicAdd(&g_count[r.y * C_REP + ((e0 + 1) & (C_REP - 1))], 1);
    }
}

// ---------------------------------------------------------------- span
// Warp per row, 8 rows per block. Fuses: replica-count reduce, row-region
// allocation (block-aggregated bump atomic), span + staggered cursor write.
// Re-zeroes g_count after reading so the next graph replay starts clean.
__global__ __launch_bounds__(256) void span_kernel(int n) {
    __shared__ int s_total[8];
    __shared__ int s_base[8];
    int wid  = threadIdx.x >> 5;
    int lane = threadIdx.x & 31;
    int r    = blockIdx.x * 8 + wid;

    int cnt = (r < n) ? g_count[r * C_REP + lane] : 0;

    int x = cnt;
    #pragma unroll
    for (int off = 1; off < 32; off <<= 1) {
        int t = __shfl_up_sync(0xffffffffu, x, off);
        if (lane >= off) x += t;
    }
    int total = __shfl_sync(0xffffffffu, x, 31);
    if (lane == 31) s_total[wid] = x;
    __syncthreads();

    if (wid == 0 && lane < 8) {
        int t = s_total[lane];
        int y = t;
        #pragma unroll
        for (int off = 1; off < 8; off <<= 1) {
            int u = __shfl_up_sync(0x000000ffu, y, off);
            if (lane >= off) y += u;
        }
        int blocktot = __shfl_sync(0x000000ffu, y, 7);
        int base = 0;
        if (lane == 7) base = atomicAdd(&g_alloc, blocktot);
        base = __shfl_sync(0x000000ffu, base, 7);
        s_base[lane] = base + (y - t);
    }
    __syncthreads();

    if (r < n) {
        int base = s_base[wid];
        g_cursor[r * C_REP + lane] = base + (x - cnt);
        g_count[r * C_REP + lane] = 0;            // clean for next replay
        if (lane == 0) g_span[r] = make_int2(base, base + total);
    }
}

// ---------------------------------------------------------------- scatter
// 2 edges/thread. Returning atomic; ~2-deep contention over 320K cursors.
// Packs val as half2(v,v) so the spmm can HFMA2 without conversion.
__global__ void scatter_kernel(const int2*   __restrict__ rows2,
                               const int2*   __restrict__ cols2,
                               const float2* __restrict__ vals2,
                               int E2) {
    int i = blockIdx.x * blockDim.x + threadIdx.x;
    if (i >= E2) return;
    int2   r = rows2[i];
    int2   c = cols2[i];
    float2 v = vals2[i];
    int e0 = 2 * i;

    unsigned h0 = __half_as_ushort(__float2half_rn(v.x));
    unsigned h1 = __half_as_ushort(__float2half_rn(v.y));

    int p0 = atomicAdd(&g_cursor[r.x * C_REP + (e0 & (C_REP - 1))], 1);
    g_pairs[p0] = make_uint2((unsigned)c.x, h0 | (h0 << 16));
    int p1 = atomicAdd(&g_cursor[r.y * C_REP + ((e0 + 1) & (C_REP - 1))], 1);
    g_pairs[p1] = make_uint2((unsigned)c.y, h1 | (h1 << 16));
}

// ---------------------------------------------------------------- spmm
// BLOCK per row: 8 warps split the edge list 8-way. Lane owns 4 features:
// gathers one uint2 (4 halves, 8B) per edge, accumulates with 2x HFMA2 in
// fp16, flushes to fp32 every 8 edges (rare F2F). Partials combined via
// smem, one STG.128 per lane by warp 0.
__global__ __launch_bounds__(256) void spmm_block_kernel(
    float4* __restrict__ out)    // [N, 32] float4
{
    __shared__ float4 s_acc[8][32];

    int row  = blockIdx.x;
    int wid  = threadIdx.x >> 5;
    int lane = threadIdx.x & 31;

    int2 se = g_span[row];

    const uint2* emb16 = (const uint2*)g_emb16;   // 32 chunks of 8B per row

    float4  accf = make_float4(0.f, 0.f, 0.f, 0.f);
    __half2 a0 = __floats2half2_rn(0.f, 0.f);
    __half2 a1 = a0;
    int k = 0;

    for (int j = se.x + wid; j < se.y; j += 8) {
        uint2 p = __ldg(&g_pairs[j]);                    // uniform across warp
        __half2 v2 = *reinterpret_cast<const __half2*>(&p.y);
        uint2 h = __ldg(emb16 + (int)p.x * 32 + lane);
        a0 = __hfma2(v2, *reinterpret_cast<const __half2*>(&h.x), a0);
        a1 = __hfma2(v2, *reinterpret_cast<const __half2*>(&h.y), a1);
        if (++k == 8) {                                  // warp-uniform branch
            float2 f0 = __half22float2(a0);
            float2 f1 = __half22float2(a1);
            accf.x += f0.x; accf.y += f0.y;
            accf.z += f1.x; accf.w += f1.y;
            a0 = __floats2half2_rn(0.f, 0.f);
            a1 = a0;
            k = 0;
        }
    }
    {   // final flush
        float2 f0 = __half22float2(a0);
        float2 f1 = __half22float2(a1);
        accf.x += f0.x; accf.y += f0.y;
        accf.z += f1.x; accf.w += f1.y;
    }

    s_acc[wid][lane] = accf;
    __syncthreads();

    if (wid == 0) {
        float4 r = s_acc[0][lane];
        #pragma unroll
        for (int w = 1; w < 8; w++) {
            float4 t = s_acc[w][lane];
            r.x += t.x; r.y += t.y; r.z += t.z; r.w += t.w;
        }
        out[row * 32 + lane] = r;          // degree-0 rows write zeros
    }
}

// ----------------------------------------------------------------- launch
extern "C" void kernel_launch(void* const* d_in, const int* in_sizes, int n_in,
                              void* d_out, int out_size) {
    const int*   adj_rows = (const int*)  d_in[0];
    const int*   adj_cols = (const int*)  d_in[1];
    const float* adj_vals = (const float*)d_in[2];
    const float* embeds   = (const float*)d_in[3];
    float*       out      = (float*)d_out;

    const int E  = in_sizes[0];          // 640000 (even)
    const int E2 = E / 2;
    const int N  = out_size / 128;       // 10000

    int n2 = N * D_FEAT / 2;             // half2 elements
    convert_kernel<<<(n2 + 255) / 256, 256>>>((const float2*)embeds, n2);

    hist_kernel<<<(E2 + 255) / 256, 256>>>((const int2*)adj_rows, E2);
    span_kernel<<<(N + 7) / 8, 256>>>(N);
    scatter_kernel<<<(E2 + 255) / 256, 256>>>(
        (const int2*)adj_rows, (const int2*)adj_cols, (const float2*)adj_vals, E2);

    spmm_block_kernel<<<N, 256>>>((float4*)out);
}

// round 13
// speedup vs baseline: 1.4544x; 1.4544x over previous
#include <cuda_runtime.h>
#include <cuda_bf16.h>
#include <cuda_fp16.h>

// GCNLayer SpMM: out[i,:] = sum_{e: rows[e]==i} vals[e] * embeds[cols[e],:]
// N=10000 nodes, E=640000 edges, D=128 features.
//
// Round-13:
//  * scatter is LSU-ISSUE bound (round-12: 3.5 ops/edge -> 15.2us, matches
//    1.82 cyc/op model). int4-vectorize (4 edges/thread) + 4B packed pairs
//    (col 16b | fp16 val 16b) -> ~2.75 ops/edge, ~11us.
//  * fp16 spmm regressed in round-12 because the data-dependent k==8 flush
//    broke unrolling (1 gather in flight). Warp-per-row with FIXED 8-edge
//    fully-unrolled predicated windows restores MLP; fp16 HFMA2 accumulate,
//    one fp32 flush per window. Traffic ~172MB -> ~15us at the ~6300 B/cyc
//    LTS cap (rounds 9/10 proved warp layouts reach that cap).
//  * no memsets: hist resets g_alloc, span re-zeroes g_count (validated
//    across graph replays in round 12).

static constexpr int MAX_N = 10000;
static constexpr int MAX_E = 640000;
static constexpr int D_FEAT = 128;
static constexpr int C_REP = 32;           // counter replication factor

__device__ int      g_count[MAX_N * C_REP];   // [row][replica] (zero at steady state)
__device__ int      g_cursor[MAX_N * C_REP];  // [row][replica] staggered cursors
__device__ int2     g_span[MAX_N];            // .x = start, .y = end (unordered CSR)
__device__ int      g_alloc;                  // bump allocator head
__device__ unsigned g_packed[MAX_E];          // col (16b) | half(val) << 16
__device__ __half   g_emb16[MAX_N * D_FEAT];  // fp16 embedding cache

// ---------------------------------------------------------------- convert
__global__ void convert_kernel(const float2* __restrict__ emb, int n2) {
    int i = blockIdx.x * blockDim.x + threadIdx.x;
    if (i < n2) {
        float2 f = emb[i];
        ((__half2*)g_emb16)[i] = __floats2half2_rn(f.x, f.y);
    }
}

// ---------------------------------------------------------------- hist
// 4 edges/thread via int4. No-return atomicAdd -> RED. Thread 0 resets the
// bump allocator for this replay.
__global__ void hist_kernel(const int4* __restrict__ rows4, int E4) {
    int i = blockIdx.x * blockDim.x + threadIdx.x;
    if (i == 0) g_alloc = 0;
    if (i < E4) {
        int4 r = rows4[i];
        int e0 = 4 * i;
        atomicAdd(&g_count[r.x * C_REP + ((e0 + 0) & (C_REP - 1))], 1);
        atomicAdd(&g_count[r.y * C_REP + ((e0 + 1) & (C_REP - 1))], 1);
        atomicAdd(&g_count[r.z * C_REP + ((e0 + 2) & (C_REP - 1))], 1);
        atomicAdd(&g_count[r.w * C_REP + ((e0 + 3) & (C_REP - 1))], 1);
    }
}

// ---------------------------------------------------------------- span
// Warp per row, 8 rows per block: replica reduce + bump-alloc + cursors.
// Re-zeroes g_count for the next graph replay.
__global__ __launch_bounds__(256) void span_kernel(int n) {
    __shared__ int s_total[8];
    __shared__ int s_base[8];
    int wid  = threadIdx.x >> 5;
    int lane = threadIdx.x & 31;
    int r    = blockIdx.x * 8 + wid;

    int cnt = (r < n) ? g_count[r * C_REP + lane] : 0;

    int x = cnt;
    #pragma unroll
    for (int off = 1; off < 32; off <<= 1) {
        int t = __shfl_up_sync(0xffffffffu, x, off);
        if (lane >= off) x += t;
    }
    int total = __shfl_sync(0xffffffffu, x, 31);
    if (lane == 31) s_total[wid] = x;
    __syncthreads();

    if (wid == 0 && lane < 8) {
        int t = s_total[lane];
        int y = t;
        #pragma unroll
        for (int off = 1; off < 8; off <<= 1) {
            int u = __shfl_up_sync(0x000000ffu, y, off);
            if (lane >= off) y += u;
        }
        int blocktot = __shfl_sync(0x000000ffu, y, 7);
        int base = 0;
        if (lane == 7) base = atomicAdd(&g_alloc, blocktot);
        base = __shfl_sync(0x000000ffu, base, 7);
        s_base[lane] = base + (y - t);
    }
    __syncthreads();

    if (r < n) {
        int base = s_base[wid];
        g_cursor[r * C_REP + lane] = base + (x - cnt);
        g_count[r * C_REP + lane] = 0;            // clean for next replay
        if (lane == 0) g_span[r] = make_int2(base, base + total);
    }
}

// ---------------------------------------------------------------- scatter
// 4 edges/thread via int4/float4; 4B packed pair stores.
__global__ void scatter_kernel(const int4*   __restrict__ rows4,
                               const int4*   __restrict__ cols4,
                               const float4* __restrict__ vals4,
                               int E4) {
    int i = blockIdx.x * blockDim.x + threadIdx.x;
    if (i >= E4) return;
    int4   r = rows4[i];
    int4   c = cols4[i];
    float4 v = vals4[i];
    int e0 = 4 * i;

    unsigned pk0 = (unsigned)c.x | ((unsigned)__half_as_ushort(__float2half_rn(v.x)) << 16);
    unsigned pk1 = (unsigned)c.y | ((unsigned)__half_as_ushort(__float2half_rn(v.y)) << 16);
    unsigned pk2 = (unsigned)c.z | ((unsigned)__half_as_ushort(__float2half_rn(v.z)) << 16);
    unsigned pk3 = (unsigned)c.w | ((unsigned)__half_as_ushort(__float2half_rn(v.w)) << 16);

    int p0 = atomicAdd(&g_cursor[r.x * C_REP + ((e0 + 0) & (C_REP - 1))], 1);
    g_packed[p0] = pk0;
    int p1 = atomicAdd(&g_cursor[r.y * C_REP + ((e0 + 1) & (C_REP - 1))], 1);
    g_packed[p1] = pk1;
    int p2 = atomicAdd(&g_cursor[r.z * C_REP + ((e0 + 2) & (C_REP - 1))], 1);
    g_packed[p2] = pk2;
    int p3 = atomicAdd(&g_cursor[r.w * C_REP + ((e0 + 3) & (C_REP - 1))], 1);
    g_packed[p3] = pk3;
}

// ---------------------------------------------------------------- spmm
// WARP per row (deg ~64 -> ~8 full windows). Fixed 8-edge fully-unrolled
// predicated windows: 8 independent 4B pair loads + 8 independent 8B
// gathers in flight; fp16 HFMA2 accumulate, fp32 flush once per window.
// Lane owns 4 features (8B of fp16 / 16B of fp32 out).
__global__ __launch_bounds__(256) void spmm_warp_kernel(
    float4* __restrict__ out,    // [N, 32] float4
    int n)
{
    int warp = (blockIdx.x * blockDim.x + threadIdx.x) >> 5;
    int lane = threadIdx.x & 31;
    if (warp >= n) return;

    int2 se = g_span[warp];

    const uint2* emb16 = (const uint2*)g_emb16;   // 32 chunks of 8B per row
    const __half2 hzero = __floats2half2_rn(0.f, 0.f);

    float4 accf = make_float4(0.f, 0.f, 0.f, 0.f);

    for (int j0 = se.x; j0 < se.y; j0 += 8) {
        __half2 a0 = hzero, a1 = hzero;
        #pragma unroll
        for (int u = 0; u < 8; u++) {
            int j = j0 + u;
            bool ok = (j < se.y);
            unsigned pk = __ldg(&g_packed[ok ? j : se.x]);   // uniform addr
            __half2 v2 = ok ? __half2half2(__ushort_as_half((unsigned short)(pk >> 16)))
                            : hzero;
            uint2 h = __ldg(emb16 + (int)(pk & 0xFFFFu) * 32 + lane);
            a0 = __hfma2(v2, *reinterpret_cast<const __half2*>(&h.x), a0);
            a1 = __hfma2(v2, *reinterpret_cast<const __half2*>(&h.y), a1);
        }
        float2 f0 = __half22float2(a0);
        float2 f1 = __half22float2(a1);
        accf.x += f0.x; accf.y += f0.y;
        accf.z += f1.x; accf.w += f1.y;
    }

    out[warp * 32 + lane] = accf;      // degree-0 rows write zeros
}

// ----------------------------------------------------------------- launch
extern "C" void kernel_launch(void* const* d_in, const int* in_sizes, int n_in,
                              void* d_out, int out_size) {
    const int*   adj_rows = (const int*)  d_in[0];
    const int*   adj_cols = (const int*)  d_in[1];
    const float* adj_vals = (const float*)d_in[2];
    const float* embeds   = (const float*)d_in[3];
    float*       out      = (float*)d_out;

    const int E  = in_sizes[0];          // 640000 (divisible by 4)
    const int E4 = E / 4;
    const int N  = out_size / 128;       // 10000

    int n2 = N * D_FEAT / 2;             // half2 elements
    convert_kernel<<<(n2 + 255) / 256, 256>>>((const float2*)embeds, n2);

    hist_kernel<<<(E4 + 255) / 256, 256>>>((const int4*)adj_rows, E4);
    span_kernel<<<(N + 7) / 8, 256>>>(N);
    scatter_kernel<<<(E4 + 255) / 256, 256>>>(
        (const int4*)adj_rows, (const int4*)adj_cols, (const float4*)adj_vals, E4);

    long long warp_threads = (long long)N * 32;
    int warp_blocks = (int)((warp_threads + 255) / 256);
    spmm_warp_kernel<<<warp_blocks, 256>>>((float4*)out, N);
}